// round 7
// baseline (speedup 1.0000x reference)
#include <cuda_runtime.h>
#include <cuda_bf16.h>
#include <cstdint>

// ---------------- problem constants ----------------
#define N      4096
#define NB     512
#define NSTEPS 64
#define DT     0.1f
#define OMDT   0.9f

#define TRAJ    ((size_t)(N + 2) * NB)
#define CONBASE ((size_t)NSTEPS * TRAJ)

// ---------------- GEMM tiling ----------------
#define BM 128
#define BN 128
#define BK 32
#define STAGES 4
#define ROWB   80                       // padded row: 32 bf16 + 8 pad = 80 bytes
#define MATB   (128 * ROWB)             // 10240 bytes per matrix tile
#define STAGEB (4 * MATB)               // Ah, Al, Bh, Bl
#define HDR    2048
#define SMEMSZ (HDR + STAGES * STAGEB)  // 165888
#define KSTEPS (N / BK)                 // 128
#define CSTRIDE 132

// ---------------- device scratch ----------------
__device__ __align__(256) __nv_bfloat16 g_Wh[(size_t)N * N];
__device__ __align__(256) __nv_bfloat16 g_Wl[(size_t)N * N];
__device__ __align__(256) __nv_bfloat16 g_hh[2][(size_t)NB * N];   // h^T hi  [b][k]
__device__ __align__(256) __nv_bfloat16 g_hl[2][(size_t)NB * N];   // h^T lo
__device__ float g_x[2][2 * NB];
__device__ float g_zp[2][64 * NB];       // 64 partial Z·h chunks per batch

// ---------------- helpers ----------------
__device__ __forceinline__ uint32_t s2u(const void* p) {
    uint32_t a;
    asm("{ .reg .u64 t; cvta.to.shared.u64 t, %1; cvt.u32.u64 %0, t; }" : "=r"(a) : "l"(p));
    return a;
}
__device__ __forceinline__ void cp16(uint32_t s, const void* g) {
    asm volatile("cp.async.cg.shared.global [%0], [%1], 16;" :: "r"(s), "l"(g));
}
#define CPCOMMIT() asm volatile("cp.async.commit_group;" ::: "memory")
#define CPWAIT2()  asm volatile("cp.async.wait_group 2;" ::: "memory")

#define MMA(c, a0, a1, a2, a3, b0, b1) \
    asm volatile( \
        "mma.sync.aligned.m16n8k16.row.col.f32.bf16.bf16.f32 " \
        "{%0,%1,%2,%3},{%4,%5,%6,%7},{%8,%9},{%0,%1,%2,%3};" \
        : "+f"((c)[0]), "+f"((c)[1]), "+f"((c)[2]), "+f"((c)[3]) \
        : "r"(a0), "r"(a1), "r"(a2), "r"(a3), "r"(b0), "r"(b1))

#define LDSM4(r0, r1, r2, r3, a) \
    asm volatile("ldmatrix.sync.aligned.m8n8.x4.shared.b16 {%0,%1,%2,%3}, [%4];" \
                 : "=r"(r0), "=r"(r1), "=r"(r2), "=r"(r3) : "r"(a))

// ---------------- one-time build kernels ----------------
__global__ void build_wp(const float* __restrict__ W, const float* __restrict__ Mv,
                         const float* __restrict__ Z, const float* __restrict__ U,
                         const float* __restrict__ V, const float* __restrict__ Bm,
                         const float* __restrict__ C)
{
    int j = blockIdx.x * 256 + threadIdx.x;
    int i = blockIdx.y;
    float cb = C[0] * Bm[0] + C[1] * Bm[1];
    float4 u = *reinterpret_cast<const float4*>(U + (size_t)i * 4);
    float4 v = *reinterpret_cast<const float4*>(V + (size_t)j * 4);
    float uv = u.x * v.x + u.y * v.y + u.z * v.z + u.w * v.w;
    float val = DT * W[(size_t)i * N + j] + cb * Mv[i] * Z[j] + DT * uv;
    if (i == j) val += OMDT;
    __nv_bfloat16 hi = __float2bfloat16(val);
    float lo = val - __bfloat162float(hi);
    size_t a = (size_t)i * N + j;
    g_Wh[a] = hi;
    g_Wl[a] = __float2bfloat16(lo);
}

__global__ void init_h(const float* __restrict__ h0, float* __restrict__ out)
{
    __shared__ float t[32][33];
    int jb = blockIdx.x * 32, bb = blockIdx.y * 32;
    int tx = threadIdx.x, ty = threadIdx.y;  // 32 x 8
#pragma unroll
    for (int r = 0; r < 4; ++r) {
        int j = jb + ty + r * 8;
        float v = h0[(size_t)j * NB + bb + tx];
        t[ty + r * 8][tx] = v;
        out[(size_t)(2 + j) * NB + bb + tx] = v;
    }
    __syncthreads();
#pragma unroll
    for (int r = 0; r < 4; ++r) {
        int b = bb + ty + r * 8;
        int j = jb + tx;
        float v = t[tx][ty + r * 8];
        __nv_bfloat16 hi = __float2bfloat16(v);
        size_t a = (size_t)b * N + j;
        g_hh[0][a] = hi;
        g_hl[0][a] = __float2bfloat16(v - __bfloat162float(hi));
    }
}

__global__ void init_zx(const float* __restrict__ h0, const float* __restrict__ Z,
                        const float* __restrict__ x0, const float* __restrict__ x1)
{
    int b = blockIdx.y * 128 + threadIdx.x;
    int j0 = blockIdx.x * 64;
    float s = 0.0f;
#pragma unroll 8
    for (int jj = 0; jj < 64; ++jj)
        s += Z[j0 + jj] * h0[(size_t)(j0 + jj) * NB + b];
    g_zp[0][blockIdx.x * NB + b] = s;
    if (blockIdx.x == 0 && blockIdx.y == 0) {
        for (int bb = threadIdx.x; bb < NB; bb += 128) {
            g_x[0][bb]      = x0[bb];
            g_x[0][NB + bb] = x1[bb];
        }
    }
}

__global__ void final_xcon(const float* __restrict__ Bm, float* __restrict__ out)
{
    int b = threadIdx.x;  // 512
    float zh = 0.0f;
#pragma unroll
    for (int c = 0; c < 64; ++c) zh += g_zp[1][c * NB + b];
    const float* xc = g_x[1];
    out[(size_t)63 * TRAJ + b]      = xc[b];
    out[(size_t)63 * TRAJ + NB + b] = xc[NB + b];
    out[CONBASE + (size_t)63 * NB + b] = Bm[1] * zh;
}

// ---------------- fused step kernel ----------------
// h_next = Wp @ h + M ⊗ cax  via 3-product bf16 split on mma.sync + ldmatrix,
// with register double-buffered fragments (software pipeline over (kh, mi)).
__global__ void __launch_bounds__(256, 1)
gemm_step(int cur, const float* __restrict__ Ain, const float* __restrict__ Bm,
          const float* __restrict__ Cin, const float* __restrict__ Mv,
          const float* __restrict__ Zv, float* __restrict__ out, int t)
{
    extern __shared__ char smem[];
    const uint32_t sb = s2u(smem);
    const int tid = threadIdx.x;
    const int lane = tid & 31;
    const int wid = tid >> 5;
    const int wm = wid >> 2, wn = wid & 3;      // 2 x 4 warp grid
    const int nt = blockIdx.x, mt = blockIdx.y; // (4, 32)
    const int m0 = mt * BM, b0t = nt * BN;
    const int nxt = cur ^ 1;

    const __nv_bfloat16* __restrict__ hh = g_hh[cur];
    const __nv_bfloat16* __restrict__ hl = g_hl[cur];
    __nv_bfloat16* __restrict__ oh = g_hh[nxt];
    __nv_bfloat16* __restrict__ ol = g_hl[nxt];

    float* cax_s = reinterpret_cast<float*>(smem + 64);     // 128 floats
    float* m_s   = reinterpret_cast<float*>(smem + 640);    // 128 floats
    float* z_s   = reinterpret_cast<float*>(smem + 1216);   // 128 floats

    // ---- prologue: cax; CTA(0,0) global x/con ----
    {
        const float* zp = g_zp[cur];
        const float* xc = g_x[cur];
        if (tid < 128) {
            float ca0 = Cin[0] * Ain[0] + Cin[1] * Ain[2];
            float ca1 = Cin[0] * Ain[1] + Cin[1] * Ain[3];
            int b = b0t + tid;
            float zh = 0.0f;
#pragma unroll
            for (int c = 0; c < 64; ++c) zh += zp[c * NB + b];
            cax_s[tid] = DT * (ca0 * xc[b] + ca1 * xc[NB + b]);
            m_s[tid] = Mv[m0 + tid];
            z_s[tid] = Zv[m0 + tid];
        }
        if (mt == 0 && nt == 0) {
            float* xn = g_x[nxt];
            float a0 = Ain[0], a1 = Ain[1], a2 = Ain[2], a3 = Ain[3];
            float bm0 = Bm[0], bm1 = Bm[1];
#pragma unroll
            for (int k = 0; k < 2; ++k) {
                int bb = tid + k * 256;
                float z2 = 0.0f;
#pragma unroll
                for (int c = 0; c < 64; ++c) z2 += zp[c * NB + bb];
                float y0 = xc[bb], y1 = xc[NB + bb];
                out[(size_t)t * TRAJ + bb]      = y0;
                out[(size_t)t * TRAJ + NB + bb] = y1;
                out[CONBASE + (size_t)t * NB + bb] = bm1 * z2;
                xn[bb]      = a0 * y0 + a1 * y1 + bm0 * z2;
                xn[NB + bb] = a2 * y0 + a3 * y1 + bm1 * z2;
            }
        }
    }
    __syncthreads();

    // cp.async mapping: 64 threads per matrix, 8 chunks each
    const int cmat = tid >> 6;
    const int clin = tid & 63;
    const char* gmat;
    if      (cmat == 0) gmat = (const char*)(g_Wh + (size_t)m0 * N);
    else if (cmat == 1) gmat = (const char*)(g_Wl + (size_t)m0 * N);
    else if (cmat == 2) gmat = (const char*)(hh + (size_t)b0t * N);
    else                gmat = (const char*)(hl + (size_t)b0t * N);
    const uint32_t sdstmat = sb + HDR + cmat * MATB;

    auto issue = [&](int ks) {
        uint32_t stb = sdstmat + (ks & 3) * STAGEB;
        size_t kb = (size_t)ks * (BK * 2);
#pragma unroll
        for (int it = 0; it < 8; ++it) {
            int idx = it * 64 + clin;
            int row = idx >> 2, chunk = idx & 3;
            cp16(stb + row * ROWB + chunk * 16,
                 gmat + (size_t)row * (N * 2) + chunk * 16 + kb);
        }
    };

#pragma unroll
    for (int p = 0; p < 3; ++p) { issue(p); CPCOMMIT(); }

    float acc[4][4][4];
#pragma unroll
    for (int mi = 0; mi < 4; ++mi)
#pragma unroll
        for (int ni = 0; ni < 4; ++ni)
#pragma unroll
            for (int r = 0; r < 4; ++r) acc[mi][ni][r] = 0.0f;

    // ldmatrix lane-address offsets (within a matrix tile, bytes)
    const int lr = lane & 7;
    const int g  = lane >> 3;     // 0..3 (matrix index within x4)
    // A: g0 (m0-7, klow) g1 (m8-15, klow) g2 (m0-7, khigh) g3 (m8-15, khigh)
    const uint32_t aoff = (uint32_t)((wm * 64 + (g & 1) * 8 + lr) * ROWB + (g >> 1) * 16);
    // B: g0 (n0-7, klow) g1 (n0-7, khigh) g2 (n8-15, klow) g3 (n8-15, khigh)
    const uint32_t boff = (uint32_t)((wn * 32 + (g >> 1) * 8 + lr) * ROWB + (g & 1) * 16);

    for (int ks = 0; ks < KSTEPS; ++ks) {
        CPWAIT2();
        __syncthreads();
        if (ks + 3 < KSTEPS) issue(ks + 3);
        CPCOMMIT();

        const uint32_t stb = sb + HDR + (ks & 3) * STAGEB;
        const uint32_t pAh = stb + aoff;
        const uint32_t pAl = stb + MATB + aoff;
        const uint32_t pBh = stb + 2 * MATB + boff;
        const uint32_t pBl = stb + 3 * MATB + boff;

        // ---- load ALL B fragments for both kh halves (16 independent LDSM) ----
        uint32_t bh[2][4][2], bl[2][4][2];
#pragma unroll
        for (int kh = 0; kh < 2; ++kh) {
            const uint32_t khb = kh * 32;
#pragma unroll
            for (int p = 0; p < 2; ++p) {
                LDSM4(bh[kh][2*p][0], bh[kh][2*p][1], bh[kh][2*p+1][0], bh[kh][2*p+1][1],
                      pBh + p * (16 * ROWB) + khb);
                LDSM4(bl[kh][2*p][0], bl[kh][2*p][1], bl[kh][2*p+1][0], bl[kh][2*p+1][1],
                      pBl + p * (16 * ROWB) + khb);
            }
        }

        // ---- A fragments: register double buffer, prefetch next (kh, mi) ----
        uint32_t ah[2][4], al[2][4];
        LDSM4(ah[0][0], ah[0][1], ah[0][2], ah[0][3], pAh);
        LDSM4(al[0][0], al[0][1], al[0][2], al[0][3], pAl);

#pragma unroll
        for (int kh = 0; kh < 2; ++kh) {
#pragma unroll
            for (int mi = 0; mi < 4; ++mi) {
                const int step = kh * 4 + mi;
                const int cb = step & 1;
                const int nb = cb ^ 1;
                if (step < 7) {
                    const int nmi = (mi + 1) & 3;
                    const int nkh = kh + (mi == 3);
                    const uint32_t off = (uint32_t)(nmi * (16 * ROWB) + nkh * 32);
                    LDSM4(ah[nb][0], ah[nb][1], ah[nb][2], ah[nb][3], pAh + off);
                    LDSM4(al[nb][0], al[nb][1], al[nb][2], al[nb][3], pAl + off);
                }
                // product-major over ni: same-acc reuse distance = 4 MMAs
#pragma unroll
                for (int ni = 0; ni < 4; ++ni)
                    MMA(acc[mi][ni], ah[cb][0], ah[cb][1], ah[cb][2], ah[cb][3],
                        bh[kh][ni][0], bh[kh][ni][1]);
#pragma unroll
                for (int ni = 0; ni < 4; ++ni)
                    MMA(acc[mi][ni], ah[cb][0], ah[cb][1], ah[cb][2], ah[cb][3],
                        bl[kh][ni][0], bl[kh][ni][1]);
#pragma unroll
                for (int ni = 0; ni < 4; ++ni)
                    MMA(acc[mi][ni], al[cb][0], al[cb][1], al[cb][2], al[cb][3],
                        bh[kh][ni][0], bh[kh][ni][1]);
            }
        }
    }
    __syncthreads();   // all compute done before Cs overwrites stage buffers

    // ---- Phase A: frags -> Cs (+ M[i]*cax[b]) ----
    float* Cs = reinterpret_cast<float*>(smem + HDR);
#pragma unroll
    for (int mi = 0; mi < 4; ++mi) {
#pragma unroll
        for (int ni = 0; ni < 4; ++ni) {
            int row = wm * 64 + mi * 16 + (lane >> 2);
            int col = wn * 32 + ni * 8 + (lane & 3) * 2;
            float* c = acc[mi][ni];
            float2 v0 = make_float2(c[0] + m_s[row] * cax_s[col],
                                    c[1] + m_s[row] * cax_s[col + 1]);
            float2 v1 = make_float2(c[2] + m_s[row + 8] * cax_s[col],
                                    c[3] + m_s[row + 8] * cax_s[col + 1]);
            *reinterpret_cast<float2*>(&Cs[row * CSTRIDE + col]) = v0;
            *reinterpret_cast<float2*>(&Cs[(row + 8) * CSTRIDE + col]) = v1;
        }
    }
    __syncthreads();

    // ---- Phase B: traj_{t+1} h rows ----
    {
        int row = tid >> 1;
        int cb = (tid & 1) * 64;
        const float* src = Cs + row * CSTRIDE + cb;
        float* dst = out + (size_t)(t + 1) * TRAJ + (size_t)(2 + m0 + row) * NB + b0t + cb;
#pragma unroll
        for (int j = 0; j < 64; j += 4)
            *reinterpret_cast<float4*>(dst + j) = *reinterpret_cast<const float4*>(src + j);
    }

    // ---- Phase C: transposed bf16 split + Z·h partials ----
    {
        int b = tid >> 1;
        int rb = (tid & 1) * 64;
        size_t base = (size_t)(b0t + b) * N + m0 + rb;
        uint32_t* ohp = reinterpret_cast<uint32_t*>(oh + base);
        uint32_t* olp = reinterpret_cast<uint32_t*>(ol + base);
        float zh = 0.0f;
#pragma unroll
        for (int r = 0; r < 64; r += 2) {
            float v0 = Cs[(rb + r) * CSTRIDE + b];
            float v1 = Cs[(rb + r + 1) * CSTRIDE + b];
            zh += z_s[rb + r] * v0 + z_s[rb + r + 1] * v1;
            __nv_bfloat16 h0 = __float2bfloat16(v0);
            __nv_bfloat16 h1 = __float2bfloat16(v1);
            __nv_bfloat16 l0 = __float2bfloat16(v0 - __bfloat162float(h0));
            __nv_bfloat16 l1 = __float2bfloat16(v1 - __bfloat162float(h1));
            ohp[r >> 1] = (uint32_t)__bfloat16_as_ushort(h0)
                        | ((uint32_t)__bfloat16_as_ushort(h1) << 16);
            olp[r >> 1] = (uint32_t)__bfloat16_as_ushort(l0)
                        | ((uint32_t)__bfloat16_as_ushort(l1) << 16);
        }
        g_zp[nxt][(mt * 2 + (tid & 1)) * NB + b0t + b] = zh;
    }
}

// ---------------- launch ----------------
extern "C" void kernel_launch(void* const* d_in, const int* in_sizes, int n_in,
                              void* d_out, int out_size)
{
    const float* x0 = (const float*)d_in[0];
    const float* x1 = (const float*)d_in[1];
    const float* h0 = (const float*)d_in[2];
    const float* A  = (const float*)d_in[3];
    const float* Bm = (const float*)d_in[4];
    const float* C  = (const float*)d_in[5];
    const float* M  = (const float*)d_in[6];
    const float* Z  = (const float*)d_in[7];
    const float* U  = (const float*)d_in[8];
    const float* V  = (const float*)d_in[9];
    const float* W  = (const float*)d_in[10];
    (void)in_sizes; (void)n_in; (void)out_size;
    float* out = (float*)d_out;

    cudaFuncSetAttribute(gemm_step, cudaFuncAttributeMaxDynamicSharedMemorySize, SMEMSZ);

    build_wp<<<dim3(N / 256, N), 256>>>(W, M, Z, U, V, Bm, C);
    init_h<<<dim3(N / 32, NB / 32), dim3(32, 8)>>>(h0, out);
    init_zx<<<dim3(64, 4), 128>>>(h0, Z, x0, x1);

    for (int t = 0; t < NSTEPS - 1; ++t)
        gemm_step<<<dim3(NB / BN, N / BM), 256, SMEMSZ>>>(t & 1, A, Bm, C, M, Z, out, t);

    final_xcon<<<1, 512>>>(Bm, out);
}

// round 8
// speedup vs baseline: 1.0561x; 1.0561x over previous
#include <cuda_runtime.h>
#include <cuda_bf16.h>
#include <cstdint>

// ---------------- problem constants ----------------
#define N      4096
#define NB     512
#define NSTEPS 64
#define DT     0.1f
#define OMDT   0.9f

#define TRAJ    ((size_t)(N + 2) * NB)
#define CONBASE ((size_t)NSTEPS * TRAJ)

// ---------------- GEMM tiling ----------------
#define BM 128
#define BN 64
#define BK 32
#define STAGES 3
#define ROWB   80                       // padded row: 32 bf16 + 8 pad = 80 bytes
#define MATA   (128 * ROWB)             // 10240 bytes (A tile: 128 rows)
#define MATBB  (64 * ROWB)              // 5120 bytes  (B tile: 64 rows)
#define OFF_AH 0
#define OFF_AL MATA
#define OFF_BH (2 * MATA)
#define OFF_BL (2 * MATA + MATBB)
#define STAGEB (2 * MATA + 2 * MATBB)   // 30720
#define HDR    2048
#define SMEMSZ (HDR + STAGES * STAGEB)  // 94208  (x2 CTAs = 188416 < 228KB)
#define KSTEPS (N / BK)                 // 128
#define CSTRIDE 68                      // Cs row stride (floats)

// ---------------- device scratch ----------------
__device__ __align__(256) __nv_bfloat16 g_Wh[(size_t)N * N];
__device__ __align__(256) __nv_bfloat16 g_Wl[(size_t)N * N];
__device__ __align__(256) __nv_bfloat16 g_hh[2][(size_t)NB * N];   // h^T hi  [b][k]
__device__ __align__(256) __nv_bfloat16 g_hl[2][(size_t)NB * N];   // h^T lo
__device__ float g_x[2][2 * NB];
__device__ float g_zp[2][64 * NB];       // 64 partial Z·h chunks (64 rows each)

// ---------------- helpers ----------------
__device__ __forceinline__ uint32_t s2u(const void* p) {
    uint32_t a;
    asm("{ .reg .u64 t; cvta.to.shared.u64 t, %1; cvt.u32.u64 %0, t; }" : "=r"(a) : "l"(p));
    return a;
}
__device__ __forceinline__ void cp16(uint32_t s, const void* g) {
    asm volatile("cp.async.cg.shared.global [%0], [%1], 16;" :: "r"(s), "l"(g));
}
#define CPCOMMIT() asm volatile("cp.async.commit_group;" ::: "memory")
#define CPWAIT1()  asm volatile("cp.async.wait_group 1;" ::: "memory")
#define CPWAIT0()  asm volatile("cp.async.wait_group 0;" ::: "memory")

#define MMA(c, a0, a1, a2, a3, b0, b1) \
    asm volatile( \
        "mma.sync.aligned.m16n8k16.row.col.f32.bf16.bf16.f32 " \
        "{%0,%1,%2,%3},{%4,%5,%6,%7},{%8,%9},{%0,%1,%2,%3};" \
        : "+f"((c)[0]), "+f"((c)[1]), "+f"((c)[2]), "+f"((c)[3]) \
        : "r"(a0), "r"(a1), "r"(a2), "r"(a3), "r"(b0), "r"(b1))

#define LDSM4(r0, r1, r2, r3, a) \
    asm volatile("ldmatrix.sync.aligned.m8n8.x4.shared.b16 {%0,%1,%2,%3}, [%4];" \
                 : "=r"(r0), "=r"(r1), "=r"(r2), "=r"(r3) : "r"(a))

// ---------------- one-time build kernels ----------------
__global__ void build_wp(const float* __restrict__ W, const float* __restrict__ Mv,
                         const float* __restrict__ Z, const float* __restrict__ U,
                         const float* __restrict__ V, const float* __restrict__ Bm,
                         const float* __restrict__ C)
{
    int j = blockIdx.x * 256 + threadIdx.x;
    int i = blockIdx.y;
    float cb = C[0] * Bm[0] + C[1] * Bm[1];
    float4 u = *reinterpret_cast<const float4*>(U + (size_t)i * 4);
    float4 v = *reinterpret_cast<const float4*>(V + (size_t)j * 4);
    float uv = u.x * v.x + u.y * v.y + u.z * v.z + u.w * v.w;
    float val = DT * W[(size_t)i * N + j] + cb * Mv[i] * Z[j] + DT * uv;
    if (i == j) val += OMDT;
    __nv_bfloat16 hi = __float2bfloat16(val);
    float lo = val - __bfloat162float(hi);
    size_t a = (size_t)i * N + j;
    g_Wh[a] = hi;
    g_Wl[a] = __float2bfloat16(lo);
}

__global__ void init_h(const float* __restrict__ h0, float* __restrict__ out)
{
    __shared__ float t[32][33];
    int jb = blockIdx.x * 32, bb = blockIdx.y * 32;
    int tx = threadIdx.x, ty = threadIdx.y;  // 32 x 8
#pragma unroll
    for (int r = 0; r < 4; ++r) {
        int j = jb + ty + r * 8;
        float v = h0[(size_t)j * NB + bb + tx];
        t[ty + r * 8][tx] = v;
        out[(size_t)(2 + j) * NB + bb + tx] = v;
    }
    __syncthreads();
#pragma unroll
    for (int r = 0; r < 4; ++r) {
        int b = bb + ty + r * 8;
        int j = jb + tx;
        float v = t[tx][ty + r * 8];
        __nv_bfloat16 hi = __float2bfloat16(v);
        size_t a = (size_t)b * N + j;
        g_hh[0][a] = hi;
        g_hl[0][a] = __float2bfloat16(v - __bfloat162float(hi));
    }
}

__global__ void init_zx(const float* __restrict__ h0, const float* __restrict__ Z,
                        const float* __restrict__ x0, const float* __restrict__ x1)
{
    int b = blockIdx.y * 128 + threadIdx.x;
    int j0 = blockIdx.x * 64;
    float s = 0.0f;
#pragma unroll 8
    for (int jj = 0; jj < 64; ++jj)
        s += Z[j0 + jj] * h0[(size_t)(j0 + jj) * NB + b];
    g_zp[0][blockIdx.x * NB + b] = s;
    if (blockIdx.x == 0 && blockIdx.y == 0) {
        for (int bb = threadIdx.x; bb < NB; bb += 128) {
            g_x[0][bb]      = x0[bb];
            g_x[0][NB + bb] = x1[bb];
        }
    }
}

__global__ void final_xcon(const float* __restrict__ Bm, float* __restrict__ out)
{
    int b = threadIdx.x;  // 512
    float zh = 0.0f;
#pragma unroll
    for (int c = 0; c < 64; ++c) zh += g_zp[1][c * NB + b];
    const float* xc = g_x[1];
    out[(size_t)63 * TRAJ + b]      = xc[b];
    out[(size_t)63 * TRAJ + NB + b] = xc[NB + b];
    out[CONBASE + (size_t)63 * NB + b] = Bm[1] * zh;
}

// ---------------- fused step kernel ----------------
// h_next = Wp @ h + M ⊗ cax  via 3-product bf16 split on mma.sync + ldmatrix.
// 128 threads, 2x2 warp grid, 64x32 per warp; 2 CTAs co-resident per SM so
// prologue/epilogue/sync bubbles of one CTA overlap the other's MMAs.
__global__ void __launch_bounds__(128, 2)
gemm_step(int cur, const float* __restrict__ Ain, const float* __restrict__ Bm,
          const float* __restrict__ Cin, const float* __restrict__ Mv,
          const float* __restrict__ Zv, float* __restrict__ out, int t)
{
    extern __shared__ char smem[];
    const uint32_t sb = s2u(smem);
    const int tid = threadIdx.x;
    const int lane = tid & 31;
    const int wid = tid >> 5;
    const int wm = wid >> 1, wn = wid & 1;      // 2 x 2 warp grid
    const int nt = blockIdx.x, mt = blockIdx.y; // (8, 32)
    const int m0 = mt * BM, b0t = nt * BN;
    const int nxt = cur ^ 1;

    const __nv_bfloat16* __restrict__ hh = g_hh[cur];
    const __nv_bfloat16* __restrict__ hl = g_hl[cur];
    __nv_bfloat16* __restrict__ oh = g_hh[nxt];
    __nv_bfloat16* __restrict__ ol = g_hl[nxt];

    float* cax_s = reinterpret_cast<float*>(smem + 64);     // 64 floats
    float* m_s   = reinterpret_cast<float*>(smem + 640);    // 128 floats
    float* z_s   = reinterpret_cast<float*>(smem + 1216);   // 128 floats

    // ---- prologue: cax; m/z row caches; CTA(0,0) global x/con ----
    {
        const float* zp = g_zp[cur];
        const float* xc = g_x[cur];
        m_s[tid] = Mv[m0 + tid];
        z_s[tid] = Zv[m0 + tid];
        if (tid < 64) {
            float ca0 = Cin[0] * Ain[0] + Cin[1] * Ain[2];
            float ca1 = Cin[0] * Ain[1] + Cin[1] * Ain[3];
            int b = b0t + tid;
            float zh = 0.0f;
#pragma unroll
            for (int c = 0; c < 64; ++c) zh += zp[c * NB + b];
            cax_s[tid] = DT * (ca0 * xc[b] + ca1 * xc[NB + b]);
        }
        if (mt == 0 && nt == 0) {
            float* xn = g_x[nxt];
            float a0 = Ain[0], a1 = Ain[1], a2 = Ain[2], a3 = Ain[3];
            float bm0 = Bm[0], bm1 = Bm[1];
#pragma unroll
            for (int k = 0; k < 4; ++k) {
                int bb = tid + k * 128;
                float z2 = 0.0f;
#pragma unroll
                for (int c = 0; c < 64; ++c) z2 += zp[c * NB + bb];
                float y0 = xc[bb], y1 = xc[NB + bb];
                out[(size_t)t * TRAJ + bb]      = y0;
                out[(size_t)t * TRAJ + NB + bb] = y1;
                out[CONBASE + (size_t)t * NB + bb] = bm1 * z2;
                xn[bb]      = a0 * y0 + a1 * y1 + bm0 * z2;
                xn[NB + bb] = a2 * y0 + a3 * y1 + bm1 * z2;
            }
        }
    }
    __syncthreads();

    const char* gAh = (const char*)(g_Wh + (size_t)m0 * N);
    const char* gAl = (const char*)(g_Wl + (size_t)m0 * N);
    const char* gBh = (const char*)(hh + (size_t)b0t * N);
    const char* gBl = (const char*)(hl + (size_t)b0t * N);

    auto issue = [&](int ks) {
        int s = ks % STAGES;
        uint32_t stb = sb + HDR + s * STAGEB;
        size_t kb = (size_t)ks * (BK * 2);
        // A tiles: 128 rows x 4 chunks = 512 cp16 per tile, 4 per thread
#pragma unroll
        for (int it = 0; it < 4; ++it) {
            int idx = it * 128 + tid;
            int row = idx >> 2, chunk = idx & 3;
            uint32_t so = (uint32_t)(row * ROWB + chunk * 16);
            size_t go = (size_t)row * (N * 2) + kb + chunk * 16;
            cp16(stb + OFF_AH + so, gAh + go);
            cp16(stb + OFF_AL + so, gAl + go);
        }
        // B tiles: 64 rows x 4 chunks = 256 cp16 per tile, 2 per thread
#pragma unroll
        for (int it = 0; it < 2; ++it) {
            int idx = it * 128 + tid;
            int row = idx >> 2, chunk = idx & 3;
            uint32_t so = (uint32_t)(row * ROWB + chunk * 16);
            size_t go = (size_t)row * (N * 2) + kb + chunk * 16;
            cp16(stb + OFF_BH + so, gBh + go);
            cp16(stb + OFF_BL + so, gBl + go);
        }
    };

#pragma unroll
    for (int p = 0; p < 2; ++p) { issue(p); CPCOMMIT(); }

    float acc[4][4][4];
#pragma unroll
    for (int mi = 0; mi < 4; ++mi)
#pragma unroll
        for (int ni = 0; ni < 4; ++ni)
#pragma unroll
            for (int r = 0; r < 4; ++r) acc[mi][ni][r] = 0.0f;

    // ldmatrix lane-address offsets (within a matrix tile, bytes)
    const int lr = lane & 7;
    const int g  = lane >> 3;     // 0..3 (matrix index within x4)
    const uint32_t aoff = (uint32_t)((wm * 64 + (g & 1) * 8 + lr) * ROWB + (g >> 1) * 16);
    const uint32_t boff = (uint32_t)((wn * 32 + (g >> 1) * 8 + lr) * ROWB + (g & 1) * 16);

    for (int ks = 0; ks < KSTEPS; ++ks) {
        CPWAIT1();
        __syncthreads();
        if (ks + 2 < KSTEPS) issue(ks + 2);
        CPCOMMIT();

        const uint32_t stb = sb + HDR + (ks % STAGES) * STAGEB;
        const uint32_t pAh = stb + OFF_AH + aoff;
        const uint32_t pAl = stb + OFF_AL + aoff;
        const uint32_t pBh = stb + OFF_BH + boff;
        const uint32_t pBl = stb + OFF_BL + boff;

        // ---- all B fragments for both kh halves ----
        uint32_t bh[2][4][2], bl[2][4][2];
#pragma unroll
        for (int kh = 0; kh < 2; ++kh) {
            const uint32_t khb = kh * 32;
#pragma unroll
            for (int p = 0; p < 2; ++p) {
                LDSM4(bh[kh][2*p][0], bh[kh][2*p][1], bh[kh][2*p+1][0], bh[kh][2*p+1][1],
                      pBh + p * (16 * ROWB) + khb);
                LDSM4(bl[kh][2*p][0], bl[kh][2*p][1], bl[kh][2*p+1][0], bl[kh][2*p+1][1],
                      pBl + p * (16 * ROWB) + khb);
            }
        }

        // ---- A fragments: register double buffer ----
        uint32_t ah[2][4], al[2][4];
        LDSM4(ah[0][0], ah[0][1], ah[0][2], ah[0][3], pAh);
        LDSM4(al[0][0], al[0][1], al[0][2], al[0][3], pAl);

#pragma unroll
        for (int kh = 0; kh < 2; ++kh) {
#pragma unroll
            for (int mi = 0; mi < 4; ++mi) {
                const int step = kh * 4 + mi;
                const int cb = step & 1;
                const int nb = cb ^ 1;
                if (step < 7) {
                    const int nmi = (mi + 1) & 3;
                    const int nkh = kh + (mi == 3);
                    const uint32_t off = (uint32_t)(nmi * (16 * ROWB) + nkh * 32);
                    LDSM4(ah[nb][0], ah[nb][1], ah[nb][2], ah[nb][3], pAh + off);
                    LDSM4(al[nb][0], al[nb][1], al[nb][2], al[nb][3], pAl + off);
                }
#pragma unroll
                for (int ni = 0; ni < 4; ++ni)
                    MMA(acc[mi][ni], ah[cb][0], ah[cb][1], ah[cb][2], ah[cb][3],
                        bh[kh][ni][0], bh[kh][ni][1]);
#pragma unroll
                for (int ni = 0; ni < 4; ++ni)
                    MMA(acc[mi][ni], ah[cb][0], ah[cb][1], ah[cb][2], ah[cb][3],
                        bl[kh][ni][0], bl[kh][ni][1]);
#pragma unroll
                for (int ni = 0; ni < 4; ++ni)
                    MMA(acc[mi][ni], al[cb][0], al[cb][1], al[cb][2], al[cb][3],
                        bh[kh][ni][0], bh[kh][ni][1]);
            }
        }
    }
    CPWAIT0();
    __syncthreads();   // all compute done before Cs overwrites stage buffers

    // ---- Phase A: frags -> Cs (+ M[i]*cax[b]) ----
    float* Cs = reinterpret_cast<float*>(smem + HDR);
#pragma unroll
    for (int mi = 0; mi < 4; ++mi) {
#pragma unroll
        for (int ni = 0; ni < 4; ++ni) {
            int row = wm * 64 + mi * 16 + (lane >> 2);
            int col = wn * 32 + ni * 8 + (lane & 3) * 2;
            float* c = acc[mi][ni];
            float2 v0 = make_float2(c[0] + m_s[row] * cax_s[col],
                                    c[1] + m_s[row] * cax_s[col + 1]);
            float2 v1 = make_float2(c[2] + m_s[row + 8] * cax_s[col],
                                    c[3] + m_s[row + 8] * cax_s[col + 1]);
            *reinterpret_cast<float2*>(&Cs[row * CSTRIDE + col]) = v0;
            *reinterpret_cast<float2*>(&Cs[(row + 8) * CSTRIDE + col]) = v1;
        }
    }
    __syncthreads();

    // ---- Phase B: traj_{t+1} h rows (one row of 64 floats per thread) ----
    {
        int row = tid;
        const float* src = Cs + row * CSTRIDE;
        float* dst = out + (size_t)(t + 1) * TRAJ + (size_t)(2 + m0 + row) * NB + b0t;
#pragma unroll
        for (int j = 0; j < 64; j += 4)
            *reinterpret_cast<float4*>(dst + j) = *reinterpret_cast<const float4*>(src + j);
    }

    // ---- Phase C: transposed bf16 split + Z·h partials ----
    {
        int b = tid >> 1;
        int rb = (tid & 1) * 64;
        size_t base = (size_t)(b0t + b) * N + m0 + rb;
        uint32_t* ohp = reinterpret_cast<uint32_t*>(oh + base);
        uint32_t* olp = reinterpret_cast<uint32_t*>(ol + base);
        float zh = 0.0f;
#pragma unroll
        for (int r = 0; r < 64; r += 2) {
            float v0 = Cs[(rb + r) * CSTRIDE + b];
            float v1 = Cs[(rb + r + 1) * CSTRIDE + b];
            zh += z_s[rb + r] * v0 + z_s[rb + r + 1] * v1;
            __nv_bfloat16 h0 = __float2bfloat16(v0);
            __nv_bfloat16 h1 = __float2bfloat16(v1);
            __nv_bfloat16 l0 = __float2bfloat16(v0 - __bfloat162float(h0));
            __nv_bfloat16 l1 = __float2bfloat16(v1 - __bfloat162float(h1));
            ohp[r >> 1] = (uint32_t)__bfloat16_as_ushort(h0)
                        | ((uint32_t)__bfloat16_as_ushort(h1) << 16);
            olp[r >> 1] = (uint32_t)__bfloat16_as_ushort(l0)
                        | ((uint32_t)__bfloat16_as_ushort(l1) << 16);
        }
        g_zp[nxt][(mt * 2 + (tid & 1)) * NB + b0t + b] = zh;
    }
}

// ---------------- launch ----------------
extern "C" void kernel_launch(void* const* d_in, const int* in_sizes, int n_in,
                              void* d_out, int out_size)
{
    const float* x0 = (const float*)d_in[0];
    const float* x1 = (const float*)d_in[1];
    const float* h0 = (const float*)d_in[2];
    const float* A  = (const float*)d_in[3];
    const float* Bm = (const float*)d_in[4];
    const float* C  = (const float*)d_in[5];
    const float* M  = (const float*)d_in[6];
    const float* Z  = (const float*)d_in[7];
    const float* U  = (const float*)d_in[8];
    const float* V  = (const float*)d_in[9];
    const float* W  = (const float*)d_in[10];
    (void)in_sizes; (void)n_in; (void)out_size;
    float* out = (float*)d_out;

    cudaFuncSetAttribute(gemm_step, cudaFuncAttributeMaxDynamicSharedMemorySize, SMEMSZ);

    build_wp<<<dim3(N / 256, N), 256>>>(W, M, Z, U, V, Bm, C);
    init_h<<<dim3(N / 32, NB / 32), dim3(32, 8)>>>(h0, out);
    init_zx<<<dim3(64, 4), 128>>>(h0, Z, x0, x1);

    for (int t = 0; t < NSTEPS - 1; ++t)
        gemm_step<<<dim3(NB / BN, N / BM), 128, SMEMSZ>>>(t & 1, A, Bm, C, M, Z, out, t);

    final_xcon<<<1, 512>>>(Bm, out);
}